// round 3
// baseline (speedup 1.0000x reference)
#include <cuda_runtime.h>
#include <math_constants.h>

#define B    32
#define C    256
#define HW   4096          // 64*64
#define HID  16
#define CHB  8             // batches per chunk
#define NCH  (B/CHB)       // 4 chunks

// scratch (allocation-free rule: __device__ globals); float4 for alignment
__device__ float  g_avg [B*C];
__device__ float  g_max [B*C];
__device__ float  g_catt[B*C];
__device__ float4 g_spavg4[B*1024];
__device__ float4 g_spmax4[B*1024];

// ---------------------------------------------------------------------------
// kA: per-(b,c) mean & max over 4096 pixels for one 8-batch chunk.
// 2048 blocks x 256 thr, float4. Pulls the chunk into L2.
// ---------------------------------------------------------------------------
__global__ __launch_bounds__(256) void kA_chanstats(const float* __restrict__ x, int b0) {
    int plane = b0 * C + blockIdx.x;           // global (b,c) plane
    const float4* xp = (const float4*)x + (size_t)plane * 1024;
    float s = 0.f, m = -CUDART_INF_F;
#pragma unroll
    for (int k = 0; k < 4; k++) {
        float4 v = xp[k * 256 + threadIdx.x];
        s += (v.x + v.y) + (v.z + v.w);
        m = fmaxf(m, fmaxf(fmaxf(v.x, v.y), fmaxf(v.z, v.w)));
    }
#pragma unroll
    for (int off = 16; off; off >>= 1) {
        s += __shfl_down_sync(0xffffffffu, s, off);
        m = fmaxf(m, __shfl_down_sync(0xffffffffu, m, off));
    }
    __shared__ float ss[8], sm[8];
    if ((threadIdx.x & 31) == 0) { ss[threadIdx.x >> 5] = s; sm[threadIdx.x >> 5] = m; }
    __syncthreads();
    if (threadIdx.x == 0) {
        float S = 0.f, M = -CUDART_INF_F;
#pragma unroll
        for (int i = 0; i < 8; i++) { S += ss[i]; M = fmaxf(M, sm[i]); }
        g_avg[plane] = S * (1.f / 4096.f);
        g_max[plane] = M;
    }
}

// ---------------------------------------------------------------------------
// kB: inline channel-MLP (redundant per block) + spatial mean/max of x*catt.
// 256 blocks x 256 thr per chunk. Block = (batch, 32-float4 pixel group);
// thread = (pixel float4, 1-of-8 channel split). x read hits L2.
// ---------------------------------------------------------------------------
__global__ __launch_bounds__(256) void kB_spstats(const float* __restrict__ x,
                                                  const float* __restrict__ w1,
                                                  const float* __restrict__ w2,
                                                  int b0) {
    int b     = b0 + (int)(blockIdx.x >> 5);
    int group = blockIdx.x & 31;
    int tid   = threadIdx.x;

    __shared__ float s_avg[C], s_mx[C], s_h[HID], sc[C];
    s_avg[tid] = g_avg[b * C + tid];
    s_mx [tid] = g_max[b * C + tid];
    __syncthreads();

    // --- MLP: ch_att = sigmoid( w2 @ (relu(w1@avg) + relu(w1@max)) ) ---
    {
        int r  = tid >> 4;
        int l16 = tid & 15;
        float pa = 0.f, pm = 0.f;
#pragma unroll
        for (int j = 0; j < 16; j++) {
            int c = l16 + j * 16;
            float w = w1[r * C + c];
            pa += w * s_avg[c];
            pm += w * s_mx[c];
        }
#pragma unroll
        for (int off = 8; off; off >>= 1) {
            pa += __shfl_down_sync(0xffffffffu, pa, off, 16);
            pm += __shfl_down_sync(0xffffffffu, pm, off, 16);
        }
        if (l16 == 0) s_h[r] = fmaxf(pa, 0.f) + fmaxf(pm, 0.f);
    }
    __syncthreads();
    {
        float acc = 0.f;
#pragma unroll
        for (int rr = 0; rr < HID; rr++) acc += s_h[rr] * w2[tid * HID + rr];
        float catt = 1.f / (1.f + expf(-acc));
        sc[tid] = catt;
        if (group == 0) g_catt[b * C + tid] = catt;   // for kC (same value from every block)
    }
    __syncthreads();

    // --- spatial stats ---
    int lane = tid & 31;
    int cs   = tid >> 5;
    int p4   = group * 32 + lane;                   // float4 idx in plane
    const float4* xp = (const float4*)x + ((size_t)(b * C) << 10) + p4;
    float4 s = make_float4(0.f, 0.f, 0.f, 0.f);
    float4 m = make_float4(-CUDART_INF_F, -CUDART_INF_F, -CUDART_INF_F, -CUDART_INF_F);
#pragma unroll 8
    for (int j = 0; j < 32; j++) {
        int c    = cs * 32 + j;
        float a  = sc[c];
        float4 v = xp[(size_t)c * 1024];
        float vx = v.x * a, vy = v.y * a, vz = v.z * a, vw = v.w * a;
        s.x += vx; s.y += vy; s.z += vz; s.w += vw;
        m.x = fmaxf(m.x, vx); m.y = fmaxf(m.y, vy);
        m.z = fmaxf(m.z, vz); m.w = fmaxf(m.w, vw);
    }
    __shared__ float4 rs[8][32], rm[8][32];
    rs[cs][lane] = s; rm[cs][lane] = m;
    __syncthreads();
    if (tid < 32) {
        float4 S = rs[0][lane], M = rm[0][lane];
#pragma unroll
        for (int i = 1; i < 8; i++) {
            float4 a4 = rs[i][lane], b4 = rm[i][lane];
            S.x += a4.x; S.y += a4.y; S.z += a4.z; S.w += a4.w;
            M.x = fmaxf(M.x, b4.x); M.y = fmaxf(M.y, b4.y);
            M.z = fmaxf(M.z, b4.z); M.w = fmaxf(M.w, b4.w);
        }
        const float inv = 1.f / (float)C;
        S.x *= inv; S.y *= inv; S.z *= inv; S.w *= inv;
        g_spavg4[b * 1024 + p4] = S;
        g_spmax4[b * 1024 + p4] = M;
    }
}

// ---------------------------------------------------------------------------
// kC: inline 7x7 conv + sigmoid (redundant per channel-group) + final apply.
// 1024 blocks x 256 thr per chunk. Block = (batch, 4-row chunk, 32-channel
// group). Phase 1: each thread computes conv for 1 of the 256 tile pixels.
// Phase 2: each thread applies catt*att to 8 channels of its float4 pixel.
// x read hits L2; output uses streaming stores.
// ---------------------------------------------------------------------------
__global__ __launch_bounds__(256) void kC_final(const float* __restrict__ x,
                                                const float* __restrict__ w_sp,
                                                float* __restrict__ out,
                                                int b0) {
    int b    = b0 + (int)(blockIdx.x >> 7);
    int rest = blockIdx.x & 127;
    int rc   = rest >> 3;          // 0..15, 4-row chunk
    int cg   = rest & 7;           // 0..7, 32-channel group
    int h0   = rc * 4;
    int tid  = threadIdx.x;

    __shared__ float sp[2][10 * 72];           // rows h0-3..h0+6, col pad 3
    __shared__ __align__(16) float s_att[256]; // conv+sigmoid for 4x64 tile
    __shared__ float sc[32];                   // catt for channel group

    for (int i = tid; i < 2 * 10 * 72; i += 256) ((float*)sp)[i] = 0.f;
    if (tid < 32) sc[tid] = g_catt[b * C + cg * 32 + tid];
    __syncthreads();

    const float* spavg = (const float*)g_spavg4;
    const float* spmax = (const float*)g_spmax4;
    for (int idx = tid; idx < 10 * 64; idx += 256) {
        int r  = idx >> 6;
        int cx = idx & 63;
        int gh = h0 + r - 3;
        if (gh >= 0 && gh < 64) {
            sp[0][r * 72 + 3 + cx] = spavg[b * HW + gh * 64 + cx];
            sp[1][r * 72 + 3 + cx] = spmax[b * HW + gh * 64 + cx];
        }
    }
    float wr[2][7][7];
#pragma unroll
    for (int i = 0; i < 2; i++)
#pragma unroll
        for (int kh = 0; kh < 7; kh++)
#pragma unroll
            for (int kw = 0; kw < 7; kw++)
                wr[i][kh][kw] = w_sp[i * 49 + kh * 7 + kw];
    __syncthreads();

    // phase 1: conv for pixel (hl, wx); tile row hl..hl+6 covers h0+hl-3..+3
    {
        int hl = tid >> 6;
        int wx = tid & 63;
        float acc = 0.f;
#pragma unroll
        for (int i = 0; i < 2; i++)
#pragma unroll
            for (int kh = 0; kh < 7; kh++) {
                const float* row = &sp[i][(hl + kh) * 72 + wx];
#pragma unroll
                for (int kw = 0; kw < 7; kw++)
                    acc += row[kw] * wr[i][kh][kw];
            }
        s_att[tid] = 1.f / (1.f + expf(-acc));
    }
    __syncthreads();

    // phase 2: apply. thread = (split 0..3, local float4 pixel 0..63)
    {
        const float4* s_att4 = (const float4*)s_att;
        int p4l   = tid & 63;
        int split = tid >> 6;
        float4 a4 = s_att4[p4l];
        int row   = p4l >> 4;
        int col4  = p4l & 15;
        size_t pxg = (size_t)(h0 + row) * 16 + col4;   // float4 idx in plane
#pragma unroll
        for (int j = 0; j < 8; j++) {
            int ci    = split * 8 + j;
            int c     = cg * 32 + ci;
            float ca  = sc[ci];
            size_t idx = (((size_t)(b * C + c)) << 10) + pxg;
            float4 v  = ((const float4*)x)[idx];
            float4 o;
            o.x = v.x * ca * a4.x;
            o.y = v.y * ca * a4.y;
            o.z = v.z * ca * a4.z;
            o.w = v.w * ca * a4.w;
            __stcs((float4*)out + idx, o);
        }
    }
}

// ---------------------------------------------------------------------------
extern "C" void kernel_launch(void* const* d_in, const int* in_sizes, int n_in,
                              void* d_out, int out_size) {
    const float* x    = (const float*)d_in[0];   // [32,256,64,64]
    const float* w1   = (const float*)d_in[1];   // [16,256]
    const float* w2   = (const float*)d_in[2];   // [256,16]
    const float* w_sp = (const float*)d_in[3];   // [1,2,7,7]
    float* out = (float*)d_out;

    for (int ch = 0; ch < NCH; ch++) {
        int b0 = ch * CHB;
        kA_chanstats<<<CHB * C, 256>>>(x, b0);
        kB_spstats  <<<CHB * 32, 256>>>(x, w1, w2, b0);
        kC_final    <<<CHB * 128, 256>>>(x, w_sp, out, b0);
    }
}